// round 2
// baseline (speedup 1.0000x reference)
#include <cuda_runtime.h>
#include <cstdint>

#define N 128
#define K 64
#define NPAR 64
#define NPAIRS 2016
#define LLRMAX 100.0f

__device__ unsigned long long g_gm_bits[K][2];

__global__ void pack_gm_kernel(const float* __restrict__ gm) {
    int i = threadIdx.x;
    if (i < K) {
        unsigned long long w0 = 0ull, w1 = 0ull;
        #pragma unroll
        for (int j = 0; j < 64; ++j) {
            if (gm[i * N + j] > 0.5f)      w0 |= (1ull << j);
            if (gm[i * N + 64 + j] > 0.5f) w1 |= (1ull << j);
        }
        g_gm_bits[i][0] = w0;
        g_gm_bits[i][1] = w1;
    }
}

__global__ __launch_bounds__(128) void osd_kernel(
    const float* __restrict__ llrs,
    const int* __restrict__ t_ptr,
    float* __restrict__ out)
{
    __shared__ float s_key[N];
    __shared__ int   s_idx[N];
    __shared__ float s_llr[N];
    __shared__ float s_llr_sort[N];
    __shared__ unsigned long long s_g0[K], s_g1[K];
    __shared__ int s_piv[K];
    __shared__ int s_p;
    __shared__ unsigned char s_mark[N];
    __shared__ int s_par[NPAR];
    __shared__ unsigned long long s_P[K];
    __shared__ float s_dinfo[K];
    __shared__ float s_dpar[NPAR];
    __shared__ unsigned int s_ub[2];
    __shared__ unsigned long long s_x[K];
    __shared__ float s_rs[128];
    __shared__ int   s_rid[128];

    const int tid = threadIdx.x;
    const int b = blockIdx.x;

    // ---- load + clip, prep sort keys ----
    float v = llrs[b * N + tid];
    v = fminf(fmaxf(v, -LLRMAX), LLRMAX);
    s_llr[tid] = v;
    s_key[tid] = fabsf(v);
    s_idx[tid] = tid;
    __syncthreads();

    // ---- bitonic sort: descending |llr|, ties by original index ascending
    // (matches stable argsort of -|llr|) ----
    for (int size = 2; size <= N; size <<= 1) {
        for (int stride = size >> 1; stride > 0; stride >>= 1) {
            int j = tid ^ stride;
            if (j > tid) {
                float ka = s_key[tid], kb = s_key[j];
                int ia = s_idx[tid], ib = s_idx[j];
                // "b comes before a" in target order?
                bool bFirst = (kb > ka) || (kb == ka && ib < ia);
                bool asc = ((tid & size) == 0);
                bool doswap = asc ? bFirst : !bFirst;
                if (doswap) {
                    s_key[tid] = kb; s_key[j] = ka;
                    s_idx[tid] = ib; s_idx[j] = ia;
                }
            }
            __syncthreads();
        }
    }
    s_llr_sort[tid] = s_llr[s_idx[tid]];
    __syncthreads();

    // ---- build bit-packed column-permuted generator rows ----
    if (tid < K) {
        const unsigned long long gw0 = g_gm_bits[tid][0];
        const unsigned long long gw1 = g_gm_bits[tid][1];
        unsigned long long r0 = 0ull, r1 = 0ull;
        #pragma unroll 4
        for (int m = 0; m < 64; ++m) {
            int c = s_idx[m];
            unsigned long long bit = (c < 64) ? ((gw0 >> c) & 1ull)
                                              : ((gw1 >> (c - 64)) & 1ull);
            r0 |= bit << m;
        }
        #pragma unroll 4
        for (int m = 0; m < 64; ++m) {
            int c = s_idx[64 + m];
            unsigned long long bit = (c < 64) ? ((gw0 >> c) & 1ull)
                                              : ((gw1 >> (c - 64)) & 1ull);
            r1 |= bit << m;
        }
        s_g0[tid] = r0; s_g1[tid] = r1;
    }
    __syncthreads();

    // ---- GF(2) Gauss-Jordan elimination, pivot = first set bit of row i ----
    for (int i = 0; i < K; ++i) {
        if (tid == 0) {
            unsigned long long w0 = s_g0[i], w1 = s_g1[i];
            int p = w0 ? (__ffsll((long long)w0) - 1)
                       : (w1 ? (__ffsll((long long)w1) + 63) : 0);
            s_p = p;
            s_piv[i] = p;
        }
        __syncthreads();
        int p = s_p;
        if (tid < K && tid != i) {
            unsigned long long bit = (p < 64) ? ((s_g0[tid] >> p) & 1ull)
                                              : ((s_g1[tid] >> (p - 64)) & 1ull);
            if (bit) { s_g0[tid] ^= s_g0[i]; s_g1[tid] ^= s_g1[i]; }
        }
        __syncthreads();
    }

    // ---- mark pivot columns, enumerate parity columns (ascending) ----
    s_mark[tid] = 0;
    __syncthreads();
    if (tid < K) s_mark[s_piv[tid]] = 1;
    __syncthreads();
    if (tid == 0) {
        int c = 0;
        for (int m = 0; m < N; ++m) if (!s_mark[m]) s_par[c++] = m;
    }
    __syncthreads();

    // ---- parity masks P_i, info flip-costs, hard-decision bits u ----
    if (tid < K) {
        unsigned long long w0 = s_g0[tid], w1 = s_g1[tid], P = 0ull;
        #pragma unroll 4
        for (int j = 0; j < NPAR; ++j) {
            int c = s_par[j];
            unsigned long long bit = (c < 64) ? ((w0 >> c) & 1ull)
                                              : ((w1 >> (c - 64)) & 1ull);
            P |= bit << j;
        }
        s_P[tid] = P;
        float li = s_llr_sort[s_piv[tid]];
        s_dinfo[tid] = fabsf(li);
        unsigned m = __ballot_sync(0xffffffffu, li > 0.0f);
        if ((tid & 31) == 0) s_ub[tid >> 5] = m;
    }
    __syncthreads();
    const unsigned long long u64 =
        (unsigned long long)s_ub[0] | ((unsigned long long)s_ub[1] << 32);

    // ---- base parity word Cp = XOR_{i: u_i=1} P_i ----
    if (tid < K) s_x[tid] = ((u64 >> tid) & 1ull) ? s_P[tid] : 0ull;
    __syncthreads();
    for (int s = 32; s > 0; s >>= 1) {
        if (tid < s) s_x[tid] ^= s_x[tid + s];
        __syncthreads();
    }
    const unsigned long long Cp = s_x[0];

    // ---- parity flip-costs: delta = llr*(2c-1) ----
    if (tid < NPAR) {
        float lp = s_llr_sort[s_par[tid]];
        float cb = (float)((Cp >> tid) & 1ull);
        s_dpar[tid] = lp * (2.0f * cb - 1.0f);
    }
    __syncthreads();

    // ---- candidate search: id 0 = base, 1..64 = singles, 65.. = pairs lex ----
    int t = 2;
    if (t_ptr) t = t_ptr[0];
    if (t < 0) t = 0;
    if (t > 2) t = 2;
    const int nC = 1 + (t >= 1 ? K : 0) + (t >= 2 ? NPAIRS : 0);

    float best = 3.4e38f;
    int bestId = 0x7fffffff;
    for (int cid = tid; cid < nC; cid += 128) {
        float sc;
        if (cid == 0) {
            sc = 0.0f;
        } else if (cid <= K) {
            int i1 = cid - 1;
            unsigned long long m = s_P[i1];
            sc = s_dinfo[i1];
            while (m) {
                int j = __ffsll((long long)m) - 1;
                sc += s_dpar[j];
                m &= m - 1;
            }
        } else {
            int pidx = cid - (K + 1);
            // i1 = largest a with base(a) <= pidx, base(a) = 63a - a(a-1)/2
            float fp = (float)pidx;
            int a = (int)((127.0f - sqrtf(16129.0f - 8.0f * fp)) * 0.5f);
            if (a < 0) a = 0;
            if (a > 62) a = 62;
            while (a > 0 && (63 * a - (a * (a - 1)) / 2) > pidx) --a;
            while (a < 62 && (63 * (a + 1) - ((a + 1) * a) / 2) <= pidx) ++a;
            int base = 63 * a - (a * (a - 1)) / 2;
            int i1 = a;
            int i2 = a + 1 + (pidx - base);
            unsigned long long m = s_P[i1] ^ s_P[i2];
            sc = s_dinfo[i1] + s_dinfo[i2];
            while (m) {
                int j = __ffsll((long long)m) - 1;
                sc += s_dpar[j];
                m &= m - 1;
            }
        }
        if (sc < best) { best = sc; bestId = cid; }   // cid strictly increases
    }
    s_rs[tid] = best;
    s_rid[tid] = bestId;
    __syncthreads();
    for (int s = 64; s > 0; s >>= 1) {
        if (tid < s) {
            float a = s_rs[tid], bb = s_rs[tid + s];
            int ia = s_rid[tid], ib = s_rid[tid + s];
            if (bb < a || (bb == a && ib < ia)) { s_rs[tid] = bb; s_rid[tid] = ib; }
        }
        __syncthreads();
    }

    // ---- decode winner, form final codeword, scatter back ----
    const int w = s_rid[0];
    unsigned long long flip = 0ull, Px = 0ull;
    if (w >= 1 && w <= K) {
        flip = 1ull << (w - 1);
        Px = s_P[w - 1];
    } else if (w > K) {
        int pidx = w - (K + 1);
        int a = 0;
        while (pidx >= 63 - a) { pidx -= 63 - a; ++a; }
        int i1 = a, i2 = a + 1 + pidx;
        flip = (1ull << i1) | (1ull << i2);
        Px = s_P[i1] ^ s_P[i2];
    }
    const unsigned long long cinfo = u64 ^ flip;
    const unsigned long long cpar = Cp ^ Px;

    if (tid < K) {
        int col = s_idx[s_piv[tid]];
        out[b * N + col] = (float)((cinfo >> tid) & 1ull);
    } else {
        int j = tid - K;
        int col = s_idx[s_par[j]];
        out[b * N + col] = (float)((cpar >> j) & 1ull);
    }
}

extern "C" void kernel_launch(void* const* d_in, const int* in_sizes, int n_in,
                              void* d_out, int out_size) {
    const float* llrs = (const float*)d_in[0];
    const float* gm   = (const float*)d_in[1];
    const int*   t    = (n_in > 2) ? (const int*)d_in[2] : nullptr;
    int bs = in_sizes[0] / N;

    pack_gm_kernel<<<1, 64>>>(gm);
    osd_kernel<<<bs, 128>>>(llrs, t, (float*)d_out);
}

// round 3
// speedup vs baseline: 1.2548x; 1.2548x over previous
#include <cuda_runtime.h>
#include <cstdint>

#define N 128
#define K 64
#define NPAIRS 2016
#define LLRMAX 100.0f
#define WPB 4
#define FULLM 0xffffffffu

__device__ unsigned long long g_gmcol[N];

__global__ void pack_gm_kernel(const float* __restrict__ gm) {
    int c = threadIdx.x;
    if (c < N) {
        unsigned long long w = 0ull;
        #pragma unroll 8
        for (int i = 0; i < K; ++i)
            if (gm[i * N + c] > 0.5f) w |= (1ull << i);
        g_gmcol[c] = w;
    }
}

__device__ __forceinline__ int nth_set(unsigned long long w0, unsigned long long w1,
                                       int cnt0, int j) {
    unsigned long long w; int base;
    if (j < cnt0) { w = w0; base = 0; }
    else          { w = w1; base = 64; j -= cnt0; }
    for (int s = 0; s < j; ++s) w &= w - 1;
    return base + __ffsll((long long)w) - 1;
}

__global__ __launch_bounds__(32 * WPB) void osd_kernel(
    const float* __restrict__ llrs,
    const int* __restrict__ t_ptr,
    float* __restrict__ out,
    int bs)
{
    __shared__ float s_key[WPB][N];
    __shared__ int   s_idx[WPB][N];
    __shared__ float s_llr[WPB][N];
    __shared__ unsigned long long s_P[WPB][K];
    __shared__ float s_dinfo[WPB][K];
    __shared__ float s_dpar[WPB][K];
    __shared__ float s_tab[WPB][8 * 256];

    const int lane = threadIdx.x & 31;
    const int w    = threadIdx.x >> 5;
    const int b    = blockIdx.x * WPB + w;
    if (b >= bs) return;                    // whole warp exits; no CTA syncs used

    float* key = s_key[w];
    int*   idx = s_idx[w];
    float* llr = s_llr[w];
    unsigned long long* P = s_P[w];
    float* dinfo = s_dinfo[w];
    float* dpar  = s_dpar[w];
    float* tab   = s_tab[w];

    // ---- load + clip ----
    #pragma unroll
    for (int q = 0; q < 4; ++q) {
        int pos = q * 32 + lane;
        float v = llrs[b * N + pos];
        v = fminf(fmaxf(v, -LLRMAX), LLRMAX);
        llr[pos] = v;
        key[pos] = fabsf(v);
        idx[pos] = pos;
    }
    __syncwarp();

    // ---- bitonic sort (desc |llr|, ties asc index == stable argsort(-|llr|)) ----
    for (int size = 2; size <= N; size <<= 1) {
        for (int stride = size >> 1; stride > 0; stride >>= 1) {
            #pragma unroll
            for (int r = 0; r < 2; ++r) {
                int p = lane + r * 32;
                int i = ((p & ~(stride - 1)) << 1) | (p & (stride - 1));
                int j = i | stride;
                float ki = key[i], kj = key[j];
                int   ii = idx[i], ij = idx[j];
                bool jFirst = (kj > ki) || (kj == ki && ij < ii);
                bool asc = ((i & size) == 0);
                if (asc ? jFirst : !jFirst) {
                    key[i] = kj; key[j] = ki;
                    idx[i] = ij; idx[j] = ii;
                }
            }
            __syncwarp();
        }
    }

    // ---- llr_sort overwrites key ----
    #pragma unroll
    for (int q = 0; q < 4; ++q) {
        int m = q * 32 + lane;
        key[m] = llr[idx[m]];
    }
    __syncwarp();

    // ---- permuted generator columns, 4 per lane, in registers ----
    unsigned long long c0 = g_gmcol[idx[lane]];
    unsigned long long c1 = g_gmcol[idx[32 + lane]];
    unsigned long long c2 = g_gmcol[idx[64 + lane]];
    unsigned long long c3 = g_gmcol[idx[96 + lane]];

    // ---- GF(2) Gauss-Jordan, column-wise, barrier-free ----
    unsigned long long pm0 = 0ull, pm1 = 0ull;
    int piv_a = 0, piv_b = 0;
    for (int i = 0; i < K; ++i) {
        unsigned long long bi = 1ull << i;
        unsigned b0 = __ballot_sync(FULLM, (c0 & bi) != 0ull);
        unsigned b1 = __ballot_sync(FULLM, (c1 & bi) != 0ull);
        unsigned b2 = __ballot_sync(FULLM, (c2 & bi) != 0ull);
        unsigned b3 = __ballot_sync(FULLM, (c3 & bi) != 0ull);
        int p;
        if      (b0) p = __ffs(b0) - 1;
        else if (b1) p = 31 + __ffs(b1);
        else if (b2) p = 63 + __ffs(b2);
        else if (b3) p = 95 + __ffs(b3);
        else         p = 0;
        int q = p >> 5, src = p & 31;
        unsigned long long myc = (q == 0) ? c0 : (q == 1) ? c1 : (q == 2) ? c2 : c3;
        unsigned long long colp = __shfl_sync(FULLM, myc, src);
        unsigned long long mask = colp & ~bi;
        if (c0 & bi) c0 ^= mask;
        if (c1 & bi) c1 ^= mask;
        if (c2 & bi) c2 ^= mask;
        if (c3 & bi) c3 ^= mask;
        if (p < 64) pm0 |= 1ull << p; else pm1 |= 1ull << (p - 64);
        if (lane == (i & 31)) { if (i < 32) piv_a = p; else piv_b = p; }
    }

    // ---- info flip-costs + hard decisions ----
    float li_a = key[piv_a];        // llr_sort at pivot of row 'lane'
    float li_b = key[piv_b];        // row 'lane+32'
    dinfo[lane]      = fabsf(li_a);
    dinfo[lane + 32] = fabsf(li_b);
    unsigned ub0 = __ballot_sync(FULLM, li_a > 0.0f);
    unsigned ub1 = __ballot_sync(FULLM, li_b > 0.0f);
    const unsigned long long u64 =
        (unsigned long long)ub0 | ((unsigned long long)ub1 << 32);

    // ---- parity positions (ascending non-pivot), 2 per lane ----
    unsigned long long nm0 = ~pm0, nm1 = ~pm1;
    int cnt0 = __popcll(nm0);
    int mj0 = nth_set(nm0, nm1, cnt0, lane);
    int mj1 = nth_set(nm0, nm1, cnt0, lane + 32);

    // ---- gather parity columns (these ARE the P matrix, column-major) ----
    unsigned long long v0, v1, v2, v3, pc0, pc1;
    {
        v0 = __shfl_sync(FULLM, c0, mj0 & 31);
        v1 = __shfl_sync(FULLM, c1, mj0 & 31);
        v2 = __shfl_sync(FULLM, c2, mj0 & 31);
        v3 = __shfl_sync(FULLM, c3, mj0 & 31);
        int q = mj0 >> 5;
        pc0 = (q == 0) ? v0 : (q == 1) ? v1 : (q == 2) ? v2 : v3;
        v0 = __shfl_sync(FULLM, c0, mj1 & 31);
        v1 = __shfl_sync(FULLM, c1, mj1 & 31);
        v2 = __shfl_sync(FULLM, c2, mj1 & 31);
        v3 = __shfl_sync(FULLM, c3, mj1 & 31);
        q = mj1 >> 5;
        pc1 = (q == 0) ? v0 : (q == 1) ? v1 : (q == 2) ? v2 : v3;
    }

    // ---- base parity bits + parity flip-costs ----
    int cb0 = (int)(__popcll(pc0 & u64) & 1ull);
    int cb1 = (int)(__popcll(pc1 & u64) & 1ull);
    unsigned cpb0 = __ballot_sync(FULLM, cb0);
    unsigned cpb1 = __ballot_sync(FULLM, cb1);
    const unsigned long long Cp =
        (unsigned long long)cpb0 | ((unsigned long long)cpb1 << 32);
    dpar[lane]      = key[mj0] * (2.0f * (float)cb0 - 1.0f);
    dpar[lane + 32] = key[mj1] * (2.0f * (float)cb1 - 1.0f);

    // ---- transpose parity columns -> P rows via ballots ----
    for (int i = 0; i < K; ++i) {
        unsigned r0 = __ballot_sync(FULLM, (pc0 >> i) & 1ull);
        unsigned r1 = __ballot_sync(FULLM, (pc1 >> i) & 1ull);
        if (lane == (i & 31))
            P[i] = (unsigned long long)r0 | ((unsigned long long)r1 << 32);
    }
    __syncwarp();

    // ---- per-byte partial-sum tables: 8 positions x 256 entries ----
    for (int e = lane; e < 8 * 256; e += 32) {
        int bpos = e >> 8;
        unsigned v = e & 255;
        const float* dp = dpar + bpos * 8;
        float s = 0.0f;
        while (v) { int bq = __ffs(v) - 1; s += dp[bq]; v &= v - 1; }
        tab[e] = s;
    }
    __syncwarp();

    // ---- candidate search ----
    int t = t_ptr ? t_ptr[0] : 2;
    if (t < 0) t = 0;
    if (t > 2) t = 2;

    float best = 0.0f;      // base candidate (no flips), id 0 — seeded on all lanes
    int bestId = 0;

    if (t >= 1) {
        for (int i1 = lane; i1 < K; i1 += 32) {
            unsigned long long m = P[i1];
            unsigned lo = (unsigned)m, hi = (unsigned)(m >> 32);
            float sc = dinfo[i1]
                + tab[         lo & 255 ] + tab[ 256 + ((lo >> 8) & 255)]
                + tab[ 512 + ((lo >> 16) & 255)] + tab[ 768 + (lo >> 24)]
                + tab[1024 + ( hi & 255)] + tab[1280 + ((hi >> 8) & 255)]
                + tab[1536 + ((hi >> 16) & 255)] + tab[1792 + (hi >> 24)];
            int cid = 1 + i1;
            if (sc < best || (sc == best && cid < bestId)) { best = sc; bestId = cid; }
        }
    }
    if (t >= 2) {
        int a = 0, rem = lane;
        while (rem >= 63 - a) { rem -= 63 - a; ++a; }
        for (int pp = lane; pp < NPAIRS; pp += 32) {
            int i1 = a, i2 = a + 1 + rem;
            unsigned long long m = P[i1] ^ P[i2];
            unsigned lo = (unsigned)m, hi = (unsigned)(m >> 32);
            float sc = dinfo[i1] + dinfo[i2]
                + tab[         lo & 255 ] + tab[ 256 + ((lo >> 8) & 255)]
                + tab[ 512 + ((lo >> 16) & 255)] + tab[ 768 + (lo >> 24)]
                + tab[1024 + ( hi & 255)] + tab[1280 + ((hi >> 8) & 255)]
                + tab[1536 + ((hi >> 16) & 255)] + tab[1792 + (hi >> 24)];
            int cid = 65 + pp;
            if (sc < best || (sc == best && cid < bestId)) { best = sc; bestId = cid; }
            rem += 32;
            while (a < 63 && rem >= 63 - a) { rem -= 63 - a; ++a; }
        }
    }

    // ---- warp-wide lexicographic (score, id) min ----
    for (int off = 16; off; off >>= 1) {
        float os = __shfl_down_sync(FULLM, best, off);
        int  oid = __shfl_down_sync(FULLM, bestId, off);
        if (os < best || (os == best && oid < bestId)) { best = os; bestId = oid; }
    }
    const int wid = __shfl_sync(FULLM, bestId, 0);

    // ---- decode winner (uniform across warp) ----
    unsigned long long flip = 0ull, Px = 0ull;
    if (wid >= 1 && wid <= K) {
        flip = 1ull << (wid - 1);
        Px = P[wid - 1];
    } else if (wid > K) {
        int pidx = wid - (K + 1), a2 = 0;
        while (pidx >= 63 - a2) { pidx -= 63 - a2; ++a2; }
        int i1 = a2, i2 = a2 + 1 + pidx;
        flip = (1ull << i1) | (1ull << i2);
        Px = P[i1] ^ P[i2];
    }
    const unsigned long long cinfo = u64 ^ flip;
    const unsigned long long cpar  = Cp ^ Px;

    // ---- scatter back to original column order ----
    float* ob = out + b * N;
    ob[idx[piv_a]] = (float)((cinfo >> lane) & 1ull);
    ob[idx[piv_b]] = (float)((cinfo >> (lane + 32)) & 1ull);
    ob[idx[mj0]]   = (float)((cpar  >> lane) & 1ull);
    ob[idx[mj1]]   = (float)((cpar  >> (lane + 32)) & 1ull);
}

extern "C" void kernel_launch(void* const* d_in, const int* in_sizes, int n_in,
                              void* d_out, int out_size) {
    const float* llrs = (const float*)d_in[0];
    const float* gm   = (const float*)d_in[1];
    const int*   t    = (n_in > 2) ? (const int*)d_in[2] : nullptr;
    int bs = in_sizes[0] / N;

    pack_gm_kernel<<<1, N>>>(gm);
    osd_kernel<<<(bs + WPB - 1) / WPB, 32 * WPB>>>(llrs, t, (float*)d_out, bs);
}

// round 5
// speedup vs baseline: 2.2951x; 1.8290x over previous
#include <cuda_runtime.h>
#include <cstdint>

#define N 128
#define K 64
#define NPAIRS 2016
#define LLRMAX 100.0f
#define FULLM 0xffffffffu

__device__ unsigned long long g_gmcol[N];

__global__ void pack_gm_kernel(const float* __restrict__ gm) {
    int c = threadIdx.x;
    if (c < N) {
        unsigned long long w = 0ull;
        #pragma unroll 8
        for (int i = 0; i < K; ++i)
            if (gm[i * N + c] > 0.5f) w |= (1ull << i);
        g_gmcol[c] = w;
    }
}

__device__ __forceinline__ int nth_set(unsigned long long w0, unsigned long long w1,
                                       int cnt0, int j) {
    unsigned long long w; int base;
    if (j < cnt0) { w = w0; base = 0; }
    else          { w = w1; base = 64; j -= cnt0; }
    for (int s = 0; s < j; ++s) w &= w - 1;
    return base + __ffsll((long long)w) - 1;
}

__global__ __launch_bounds__(128) void osd_kernel(
    const float* __restrict__ llrs,
    const int* __restrict__ t_ptr,
    float* __restrict__ out)
{
    __shared__ float s_key[N];
    __shared__ int   s_idx[N];
    __shared__ float s_llr[N];
    __shared__ unsigned long long s_P[K];
    __shared__ float s_dinfo[K];
    __shared__ float s_dpar[K];
    __shared__ float s_tab[8 * 256];
    __shared__ unsigned long long s_u, s_Cp;
    __shared__ float s_bsc[4];
    __shared__ int   s_bid[4];
    __shared__ int   s_win;

    const int tid  = threadIdx.x;
    const int lane = tid & 31;
    const int wrp  = tid >> 5;
    const int b    = blockIdx.x;

    // ---- all threads: load + clip ----
    {
        float v = llrs[b * N + tid];
        v = fminf(fmaxf(v, -LLRMAX), LLRMAX);
        s_llr[tid] = v;
        s_key[tid] = fabsf(v);
        s_idx[tid] = tid;
    }
    __syncthreads();

    int piv_a = 0, piv_b = 0, mj0 = 0, mj1 = 0;

    if (wrp == 0) {
        // ---- bitonic sort (desc |llr|, ties asc index) — warp 0 only ----
        for (int size = 2; size <= N; size <<= 1) {
            for (int stride = size >> 1; stride > 0; stride >>= 1) {
                #pragma unroll
                for (int r = 0; r < 2; ++r) {
                    int p = lane + r * 32;
                    int i = ((p & ~(stride - 1)) << 1) | (p & (stride - 1));
                    int j = i | stride;
                    float ki = s_key[i], kj = s_key[j];
                    int   ii = s_idx[i], ij = s_idx[j];
                    bool jFirst = (kj > ki) || (kj == ki && ij < ii);
                    bool asc = ((i & size) == 0);
                    if (asc ? jFirst : !jFirst) {
                        s_key[i] = kj; s_key[j] = ki;
                        s_idx[i] = ij; s_idx[j] = ii;
                    }
                }
                __syncwarp();
            }
        }

        // llr_sort overwrites s_key
        #pragma unroll
        for (int q = 0; q < 4; ++q) {
            int m = q * 32 + lane;
            s_key[m] = s_llr[s_idx[m]];
        }
        __syncwarp();

        // ---- permuted generator columns, 4 per lane, in registers ----
        unsigned long long c0 = g_gmcol[s_idx[lane]];
        unsigned long long c1 = g_gmcol[s_idx[32 + lane]];
        unsigned long long c2 = g_gmcol[s_idx[64 + lane]];
        unsigned long long c3 = g_gmcol[s_idx[96 + lane]];

        // ---- GF(2) Gauss-Jordan, column-wise, barrier-free ----
        unsigned long long pm0 = 0ull, pm1 = 0ull;
        for (int i = 0; i < K; ++i) {
            unsigned long long bi = 1ull << i;
            unsigned b0 = __ballot_sync(FULLM, (c0 & bi) != 0ull);
            unsigned b1 = __ballot_sync(FULLM, (c1 & bi) != 0ull);
            int p;
            if (b0 | b1) {
                p = b0 ? (__ffs(b0) - 1) : (31 + __ffs(b1));
            } else {
                unsigned b2 = __ballot_sync(FULLM, (c2 & bi) != 0ull);
                unsigned b3 = __ballot_sync(FULLM, (c3 & bi) != 0ull);
                p = b2 ? (63 + __ffs(b2)) : (b3 ? (95 + __ffs(b3)) : 0);
            }
            int q = p >> 5, src = p & 31;
            unsigned long long myc = (q == 0) ? c0 : (q == 1) ? c1 : (q == 2) ? c2 : c3;
            unsigned long long colp = __shfl_sync(FULLM, myc, src);
            unsigned long long mask = colp & ~bi;
            if (c0 & bi) c0 ^= mask;
            if (c1 & bi) c1 ^= mask;
            if (c2 & bi) c2 ^= mask;
            if (c3 & bi) c3 ^= mask;
            if (p < 64) pm0 |= 1ull << p; else pm1 |= 1ull << (p - 64);
            if (lane == (i & 31)) { if (i < 32) piv_a = p; else piv_b = p; }
        }

        // ---- info flip-costs + hard decisions ----
        float li_a = s_key[piv_a];
        float li_b = s_key[piv_b];
        s_dinfo[lane]      = fabsf(li_a);
        s_dinfo[lane + 32] = fabsf(li_b);
        unsigned ub0 = __ballot_sync(FULLM, li_a > 0.0f);
        unsigned ub1 = __ballot_sync(FULLM, li_b > 0.0f);
        unsigned long long u64 =
            (unsigned long long)ub0 | ((unsigned long long)ub1 << 32);
        if (lane == 0) s_u = u64;

        // ---- parity positions (ascending non-pivot), 2 per lane ----
        unsigned long long nm0 = ~pm0, nm1 = ~pm1;
        int cnt0 = __popcll(nm0);
        mj0 = nth_set(nm0, nm1, cnt0, lane);
        mj1 = nth_set(nm0, nm1, cnt0, lane + 32);

        // ---- gather parity columns ----
        unsigned long long pc0, pc1;
        {
            unsigned long long v0 = __shfl_sync(FULLM, c0, mj0 & 31);
            unsigned long long v1 = __shfl_sync(FULLM, c1, mj0 & 31);
            unsigned long long v2 = __shfl_sync(FULLM, c2, mj0 & 31);
            unsigned long long v3 = __shfl_sync(FULLM, c3, mj0 & 31);
            int q = mj0 >> 5;
            pc0 = (q == 0) ? v0 : (q == 1) ? v1 : (q == 2) ? v2 : v3;
            v0 = __shfl_sync(FULLM, c0, mj1 & 31);
            v1 = __shfl_sync(FULLM, c1, mj1 & 31);
            v2 = __shfl_sync(FULLM, c2, mj1 & 31);
            v3 = __shfl_sync(FULLM, c3, mj1 & 31);
            q = mj1 >> 5;
            pc1 = (q == 0) ? v0 : (q == 1) ? v1 : (q == 2) ? v2 : v3;
        }

        // ---- base parity bits + parity flip-costs ----
        int cb0 = (int)(__popcll(pc0 & u64) & 1ull);
        int cb1 = (int)(__popcll(pc1 & u64) & 1ull);
        unsigned cpb0 = __ballot_sync(FULLM, cb0);
        unsigned cpb1 = __ballot_sync(FULLM, cb1);
        if (lane == 0)
            s_Cp = (unsigned long long)cpb0 | ((unsigned long long)cpb1 << 32);
        s_dpar[lane]      = s_key[mj0] * (2.0f * (float)cb0 - 1.0f);
        s_dpar[lane + 32] = s_key[mj1] * (2.0f * (float)cb1 - 1.0f);

        // ---- transpose parity columns -> P rows via ballots ----
        for (int i = 0; i < K; ++i) {
            unsigned r0 = __ballot_sync(FULLM, (pc0 >> i) & 1ull);
            unsigned r1 = __ballot_sync(FULLM, (pc1 >> i) & 1ull);
            if (lane == (i & 31))
                s_P[i] = (unsigned long long)r0 | ((unsigned long long)r1 << 32);
        }
    }
    __syncthreads();

    // ---- per-byte partial-sum tables: built by all 128 threads ----
    for (int e = tid; e < 8 * 256; e += 128) {
        int bpos = e >> 8;
        unsigned vv = e & 255;
        const float* dp = s_dpar + bpos * 8;
        float s = 0.0f;
        while (vv) { int bq = __ffs(vv) - 1; s += dp[bq]; vv &= vv - 1; }
        s_tab[e] = s;
    }
    __syncthreads();

    // ---- candidate search across all 128 threads ----
    int t = t_ptr ? t_ptr[0] : 2;
    if (t < 0) t = 0;
    if (t > 2) t = 2;

    float best = 0.0f;      // base candidate id 0 seeded everywhere
    int bestId = 0;

    if (t >= 1 && tid < K) {
        int i1 = tid;
        unsigned long long m = s_P[i1];
        unsigned lo = (unsigned)m, hi = (unsigned)(m >> 32);
        float t0 = s_tab[         lo & 255 ] + s_tab[ 256 + ((lo >> 8) & 255)];
        float t1 = s_tab[ 512 + ((lo >> 16) & 255)] + s_tab[ 768 + (lo >> 24)];
        float t2 = s_tab[1024 + ( hi & 255)] + s_tab[1280 + ((hi >> 8) & 255)];
        float t3 = s_tab[1536 + ((hi >> 16) & 255)] + s_tab[1792 + (hi >> 24)];
        float sc = s_dinfo[i1] + ((t0 + t1) + (t2 + t3));
        if (sc < best) { best = sc; bestId = 1 + i1; }
    }
    if (t >= 2) {
        int a = 0, rem = tid;
        while (rem >= 63 - a) { rem -= 63 - a; ++a; }
        for (int pp = tid; pp < NPAIRS; pp += 128) {
            int i1 = a, i2 = a + 1 + rem;
            unsigned long long m = s_P[i1] ^ s_P[i2];
            unsigned lo = (unsigned)m, hi = (unsigned)(m >> 32);
            float t0 = s_tab[         lo & 255 ] + s_tab[ 256 + ((lo >> 8) & 255)];
            float t1 = s_tab[ 512 + ((lo >> 16) & 255)] + s_tab[ 768 + (lo >> 24)];
            float t2 = s_tab[1024 + ( hi & 255)] + s_tab[1280 + ((hi >> 8) & 255)];
            float t3 = s_tab[1536 + ((hi >> 16) & 255)] + s_tab[1792 + (hi >> 24)];
            float sc = (s_dinfo[i1] + s_dinfo[i2]) + ((t0 + t1) + (t2 + t3));
            if (sc < best) { best = sc; bestId = 65 + pp; }  // pp ascending per lane
            rem += 128;
            while (a < 63 && rem >= 63 - a) { rem -= 63 - a; ++a; }
        }
    }

    // ---- warp reduce then CTA reduce, lexicographic (score, id) ----
    for (int off = 16; off; off >>= 1) {
        float os = __shfl_down_sync(FULLM, best, off);
        int  oid = __shfl_down_sync(FULLM, bestId, off);
        if (os < best || (os == best && oid < bestId)) { best = os; bestId = oid; }
    }
    if (lane == 0) { s_bsc[wrp] = best; s_bid[wrp] = bestId; }
    __syncthreads();
    if (tid == 0) {
        float bb = s_bsc[0]; int bi = s_bid[0];
        #pragma unroll
        for (int q = 1; q < 4; ++q) {
            float os = s_bsc[q]; int oid = s_bid[q];
            if (os < bb || (os == bb && oid < bi)) { bb = os; bi = oid; }
        }
        s_win = bi;
    }
    __syncthreads();

    // ---- warp 0: decode winner + scatter ----
    if (wrp == 0) {
        const int w = s_win;
        unsigned long long flip = 0ull, Px = 0ull;
        if (w >= 1 && w <= K) {
            flip = 1ull << (w - 1);
            Px = s_P[w - 1];
        } else if (w > K) {
            int pidx = w - (K + 1), a2 = 0;
            while (pidx >= 63 - a2) { pidx -= 63 - a2; ++a2; }
            int i1 = a2, i2 = a2 + 1 + pidx;
            flip = (1ull << i1) | (1ull << i2);
            Px = s_P[i1] ^ s_P[i2];
        }
        const unsigned long long cinfo = s_u ^ flip;
        const unsigned long long cpar  = s_Cp ^ Px;

        float* ob = out + b * N;
        ob[s_idx[piv_a]] = (float)((cinfo >> lane) & 1ull);
        ob[s_idx[piv_b]] = (float)((cinfo >> (lane + 32)) & 1ull);
        ob[s_idx[mj0]]   = (float)((cpar  >> lane) & 1ull);
        ob[s_idx[mj1]]   = (float)((cpar  >> (lane + 32)) & 1ull);
    }
}

extern "C" void kernel_launch(void* const* d_in, const int* in_sizes, int n_in,
                              void* d_out, int out_size) {
    const float* llrs = (const float*)d_in[0];
    const float* gm   = (const float*)d_in[1];
    const int*   t    = (n_in > 2) ? (const int*)d_in[2] : nullptr;
    int bs = in_sizes[0] / N;

    pack_gm_kernel<<<1, N>>>(gm);
    osd_kernel<<<bs, 128>>>(llrs, t, (float*)d_out);
}

// round 6
// speedup vs baseline: 2.8072x; 1.2231x over previous
#include <cuda_runtime.h>
#include <cstdint>

#define N 128
#define K 64
#define NPAIRS 2016
#define LLRMAX 100.0f
#define FULLM 0xffffffffu

__device__ __forceinline__ int nth_set(unsigned long long w0, unsigned long long w1,
                                       int cnt0, int j) {
    unsigned long long w; int base;
    if (j < cnt0) { w = w0; base = 0; }
    else          { w = w1; base = 64; j -= cnt0; }
    for (int s = 0; s < j; ++s) w &= w - 1;
    return base + __ffsll((long long)w) - 1;
}

__global__ __launch_bounds__(128) void osd_kernel(
    const float* __restrict__ llrs,
    const float* __restrict__ gm,
    const int* __restrict__ t_ptr,
    float* __restrict__ out)
{
    __shared__ float s_llr[N];
    __shared__ float s_key[N];          // llr_sort after sort
    __shared__ int   s_idx[N];
    __shared__ unsigned long long s_gmcol[N];
    __shared__ unsigned long long s_exch[N];
    __shared__ unsigned long long s_P[K];
    __shared__ float s_dinfo[K];
    __shared__ float s_dpar[K];
    __shared__ float s_tab[8 * 256];
    __shared__ unsigned long long s_u, s_Cp;
    __shared__ float s_bsc[4];
    __shared__ int   s_bid[4];
    __shared__ int   s_win;

    const int tid  = threadIdx.x;
    const int lane = tid & 31;
    const int wrp  = tid >> 5;
    const int b    = blockIdx.x;

    // ---- hoisted t load (latency overlapped with everything below) ----
    int t = 2;
    if (t_ptr) t = t_ptr[0];
    if (t < 0) t = 0;
    if (t > 2) t = 2;

    // ---- load + clip llr; build packed sort key in register ----
    float v = llrs[b * N + tid];
    v = fminf(fmaxf(v, -LLRMAX), LLRMAX);
    s_llr[tid] = v;
    unsigned long long skey =
        ((unsigned long long)__float_as_uint(fabsf(v)) << 32) |
        (unsigned long long)(127 - tid);

    // ---- pack generator column 'tid' (coalesced row-sweeps) ----
    {
        unsigned long long w = 0ull;
        #pragma unroll
        for (int i = 0; i < K; ++i)
            if (gm[i * N + tid] > 0.5f) w |= (1ull << i);
        s_gmcol[tid] = w;
    }

    // ---- 128-thread register bitonic sort (desc key) ----
    for (int size = 2; size <= N; size <<= 1) {
        const bool ascending = (tid & size) != 0;
        for (int stride = size >> 1; stride > 0; stride >>= 1) {
            unsigned long long other;
            if (stride >= 32) {
                __syncthreads();
                s_exch[tid] = skey;
                __syncthreads();
                other = s_exch[tid ^ stride];
            } else {
                other = __shfl_xor_sync(FULLM, skey, stride);
            }
            const bool iAmLower = (tid & stride) == 0;
            unsigned long long mx = skey > other ? skey : other;
            unsigned long long mn = skey > other ? other : skey;
            skey = (ascending == iAmLower) ? mn : mx;
        }
    }
    // decode sorted position
    {
        int orig = 127 - (int)(skey & 0xffffffffull);
        s_idx[tid] = orig;
        s_key[tid] = s_llr[orig];
    }
    __syncthreads();

    int piv_a = 0, piv_b = 0, mj0 = 0, mj1 = 0;

    if (wrp == 0) {
        // ---- permuted generator columns, 4 per lane, in registers ----
        unsigned long long c0 = s_gmcol[s_idx[lane]];
        unsigned long long c1 = s_gmcol[s_idx[32 + lane]];
        unsigned long long c2 = s_gmcol[s_idx[64 + lane]];
        unsigned long long c3 = s_gmcol[s_idx[96 + lane]];

        // ---- GF(2) Gauss-Jordan, column-wise, barrier-free ----
        unsigned long long pm0 = 0ull, pm1 = 0ull;
        for (int i = 0; i < K; ++i) {
            unsigned long long bi = 1ull << i;
            unsigned b0 = __ballot_sync(FULLM, (c0 & bi) != 0ull);
            unsigned b1 = __ballot_sync(FULLM, (c1 & bi) != 0ull);
            int p;
            if (b0 | b1) {
                p = b0 ? (__ffs(b0) - 1) : (31 + __ffs(b1));
            } else {
                unsigned b2 = __ballot_sync(FULLM, (c2 & bi) != 0ull);
                unsigned b3 = __ballot_sync(FULLM, (c3 & bi) != 0ull);
                p = b2 ? (63 + __ffs(b2)) : (b3 ? (95 + __ffs(b3)) : 0);
            }
            int q = p >> 5, src = p & 31;
            unsigned long long myc = (q == 0) ? c0 : (q == 1) ? c1 : (q == 2) ? c2 : c3;
            unsigned long long colp = __shfl_sync(FULLM, myc, src);
            unsigned long long mask = colp & ~bi;
            if (c0 & bi) c0 ^= mask;
            if (c1 & bi) c1 ^= mask;
            if (c2 & bi) c2 ^= mask;
            if (c3 & bi) c3 ^= mask;
            if (p < 64) pm0 |= 1ull << p; else pm1 |= 1ull << (p - 64);
            if (lane == (i & 31)) { if (i < 32) piv_a = p; else piv_b = p; }
        }

        // ---- info flip-costs + hard decisions ----
        float li_a = s_key[piv_a];
        float li_b = s_key[piv_b];
        s_dinfo[lane]      = fabsf(li_a);
        s_dinfo[lane + 32] = fabsf(li_b);
        unsigned ub0 = __ballot_sync(FULLM, li_a > 0.0f);
        unsigned ub1 = __ballot_sync(FULLM, li_b > 0.0f);
        unsigned long long u64 =
            (unsigned long long)ub0 | ((unsigned long long)ub1 << 32);
        if (lane == 0) s_u = u64;

        // ---- parity positions (ascending non-pivot), 2 per lane ----
        unsigned long long nm0 = ~pm0, nm1 = ~pm1;
        int cnt0 = __popcll(nm0);
        mj0 = nth_set(nm0, nm1, cnt0, lane);
        mj1 = nth_set(nm0, nm1, cnt0, lane + 32);

        // ---- gather parity columns ----
        unsigned long long pc0, pc1;
        {
            unsigned long long v0 = __shfl_sync(FULLM, c0, mj0 & 31);
            unsigned long long v1 = __shfl_sync(FULLM, c1, mj0 & 31);
            unsigned long long v2 = __shfl_sync(FULLM, c2, mj0 & 31);
            unsigned long long v3 = __shfl_sync(FULLM, c3, mj0 & 31);
            int q = mj0 >> 5;
            pc0 = (q == 0) ? v0 : (q == 1) ? v1 : (q == 2) ? v2 : v3;
            v0 = __shfl_sync(FULLM, c0, mj1 & 31);
            v1 = __shfl_sync(FULLM, c1, mj1 & 31);
            v2 = __shfl_sync(FULLM, c2, mj1 & 31);
            v3 = __shfl_sync(FULLM, c3, mj1 & 31);
            q = mj1 >> 5;
            pc1 = (q == 0) ? v0 : (q == 1) ? v1 : (q == 2) ? v2 : v3;
        }

        // ---- base parity bits + parity flip-costs ----
        int cb0 = (int)(__popcll(pc0 & u64) & 1ull);
        int cb1 = (int)(__popcll(pc1 & u64) & 1ull);
        unsigned cpb0 = __ballot_sync(FULLM, cb0);
        unsigned cpb1 = __ballot_sync(FULLM, cb1);
        if (lane == 0)
            s_Cp = (unsigned long long)cpb0 | ((unsigned long long)cpb1 << 32);
        s_dpar[lane]      = s_key[mj0] * (2.0f * (float)cb0 - 1.0f);
        s_dpar[lane + 32] = s_key[mj1] * (2.0f * (float)cb1 - 1.0f);

        // ---- transpose parity columns -> P rows via ballots ----
        for (int i = 0; i < K; ++i) {
            unsigned r0 = __ballot_sync(FULLM, (pc0 >> i) & 1ull);
            unsigned r1 = __ballot_sync(FULLM, (pc1 >> i) & 1ull);
            if (lane == (i & 31))
                s_P[i] = (unsigned long long)r0 | ((unsigned long long)r1 << 32);
        }
    }
    __syncthreads();

    // ---- per-byte partial-sum tables: built by all 128 threads ----
    for (int e = tid; e < 8 * 256; e += 128) {
        int bpos = e >> 8;
        unsigned vv = e & 255;
        const float* dp = s_dpar + bpos * 8;
        float s = 0.0f;
        while (vv) { int bq = __ffs(vv) - 1; s += dp[bq]; vv &= vv - 1; }
        s_tab[e] = s;
    }
    __syncthreads();

    // ---- candidate search across all 128 threads ----
    float best = 0.0f;      // base candidate id 0 seeded everywhere
    int bestId = 0;

    if (t >= 1 && tid < K) {
        int i1 = tid;
        unsigned long long m = s_P[i1];
        unsigned lo = (unsigned)m, hi = (unsigned)(m >> 32);
        float t0 = s_tab[         lo & 255 ] + s_tab[ 256 + ((lo >> 8) & 255)];
        float t1 = s_tab[ 512 + ((lo >> 16) & 255)] + s_tab[ 768 + (lo >> 24)];
        float t2 = s_tab[1024 + ( hi & 255)] + s_tab[1280 + ((hi >> 8) & 255)];
        float t3 = s_tab[1536 + ((hi >> 16) & 255)] + s_tab[1792 + (hi >> 24)];
        float sc = s_dinfo[i1] + ((t0 + t1) + (t2 + t3));
        if (sc < best) { best = sc; bestId = 1 + i1; }
    }
    if (t >= 2) {
        int a = 0, rem = tid;
        while (rem >= 63 - a) { rem -= 63 - a; ++a; }
        for (int pp = tid; pp < NPAIRS; pp += 128) {
            int i1 = a, i2 = a + 1 + rem;
            unsigned long long m = s_P[i1] ^ s_P[i2];
            unsigned lo = (unsigned)m, hi = (unsigned)(m >> 32);
            float t0 = s_tab[         lo & 255 ] + s_tab[ 256 + ((lo >> 8) & 255)];
            float t1 = s_tab[ 512 + ((lo >> 16) & 255)] + s_tab[ 768 + (lo >> 24)];
            float t2 = s_tab[1024 + ( hi & 255)] + s_tab[1280 + ((hi >> 8) & 255)];
            float t3 = s_tab[1536 + ((hi >> 16) & 255)] + s_tab[1792 + (hi >> 24)];
            float sc = (s_dinfo[i1] + s_dinfo[i2]) + ((t0 + t1) + (t2 + t3));
            if (sc < best) { best = sc; bestId = 65 + pp; }  // pp ascending per lane
            rem += 128;
            while (a < 63 && rem >= 63 - a) { rem -= 63 - a; ++a; }
        }
    }

    // ---- warp reduce then CTA reduce, lexicographic (score, id) ----
    for (int off = 16; off; off >>= 1) {
        float os = __shfl_down_sync(FULLM, best, off);
        int  oid = __shfl_down_sync(FULLM, bestId, off);
        if (os < best || (os == best && oid < bestId)) { best = os; bestId = oid; }
    }
    if (lane == 0) { s_bsc[wrp] = best; s_bid[wrp] = bestId; }
    __syncthreads();
    if (tid == 0) {
        float bb = s_bsc[0]; int bi = s_bid[0];
        #pragma unroll
        for (int q = 1; q < 4; ++q) {
            float os = s_bsc[q]; int oid = s_bid[q];
            if (os < bb || (os == bb && oid < bi)) { bb = os; bi = oid; }
        }
        s_win = bi;
    }
    __syncthreads();

    // ---- warp 0: decode winner + scatter ----
    if (wrp == 0) {
        const int w = s_win;
        unsigned long long flip = 0ull, Px = 0ull;
        if (w >= 1 && w <= K) {
            flip = 1ull << (w - 1);
            Px = s_P[w - 1];
        } else if (w > K) {
            int pidx = w - (K + 1), a2 = 0;
            while (pidx >= 63 - a2) { pidx -= 63 - a2; ++a2; }
            int i1 = a2, i2 = a2 + 1 + pidx;
            flip = (1ull << i1) | (1ull << i2);
            Px = s_P[i1] ^ s_P[i2];
        }
        const unsigned long long cinfo = s_u ^ flip;
        const unsigned long long cpar  = s_Cp ^ Px;

        float* ob = out + b * N;
        ob[s_idx[piv_a]] = (float)((cinfo >> lane) & 1ull);
        ob[s_idx[piv_b]] = (float)((cinfo >> (lane + 32)) & 1ull);
        ob[s_idx[mj0]]   = (float)((cpar  >> lane) & 1ull);
        ob[s_idx[mj1]]   = (float)((cpar  >> (lane + 32)) & 1ull);
    }
}

extern "C" void kernel_launch(void* const* d_in, const int* in_sizes, int n_in,
                              void* d_out, int out_size) {
    const float* llrs = (const float*)d_in[0];
    const float* gm   = (const float*)d_in[1];
    const int*   t    = (n_in > 2) ? (const int*)d_in[2] : nullptr;
    int bs = in_sizes[0] / N;

    osd_kernel<<<bs, 128>>>(llrs, gm, t, (float*)d_out);
}